// round 17
// baseline (speedup 1.0000x reference)
#include <cuda_runtime.h>

#define ROWS 8
#define THREADS 512
#define D 4096

typedef unsigned long long u64;

// H-folded, pre-scaled inner matrices: C[s][n] = (B[s][n] @ H64) / 64
__device__ float g_C[2 * 64 * 64 * 64];

__device__ __forceinline__ u64 pack2(float x) {
    u64 r; asm("mov.b64 %0,{%1,%1};" : "=l"(r) : "f"(x)); return r;
}
__device__ __forceinline__ void fma2(u64& d, u64 a, u64 b) {
    asm("fma.rn.f32x2 %0,%1,%2,%3;" : "=l"(d) : "l"(a), "l"(b), "l"(d));
}
// bank-conflict-avoiding swizzle: logical (block n, col c) -> physical col
__device__ __forceinline__ int swz(int n, int c) {
    return n * 64 + (c ^ ((n & 7) << 3));
}

// ---------------- prepass: C = (B @ H64) / 64 ----------------
__global__ void prep_kernel(const float* __restrict__ innerB) {
    const int t = blockIdx.x * blockDim.x + threadIdx.x;   // row of a 64x64 block
    const float4* src = reinterpret_cast<const float4*>(innerB + (size_t)t * 64);
    float v[64];
    #pragma unroll
    for (int k = 0; k < 16; k++) {
        float4 f = src[k];
        v[4*k] = f.x; v[4*k+1] = f.y; v[4*k+2] = f.z; v[4*k+3] = f.w;
    }
    #pragma unroll
    for (int h = 1; h < 64; h <<= 1)
        #pragma unroll
        for (int m = 0; m < 64; m += 2*h)
            #pragma unroll
            for (int k = 0; k < h; k++) {
                float a = v[m+k], b = v[m+k+h];
                v[m+k] = a + b; v[m+k+h] = a - b;
            }
    float4* dst = reinterpret_cast<float4*>(g_C + (size_t)t * 64);
    const float s = 1.0f / 64.0f;
    #pragma unroll
    for (int k = 0; k < 16; k++)
        dst[k] = make_float4(v[4*k]*s, v[4*k+1]*s, v[4*k+2]*s, v[4*k+3]*s);
}

// load a 4-j slab: S[jj][0..1] = row (J0+jj) cols [OBX..OBX+8)
#define LOADC4(S, BASE, STRIDE, J0, OBX)                                             \
    {                                                                                \
        _Pragma("unroll")                                                            \
        for (int jj_ = 0; jj_ < 4; jj_++) {                                          \
            S[jj_][0] = *reinterpret_cast<const ulonglong2*>(                        \
                &(BASE)[((J0) + jj_) * (STRIDE) + (OBX)]);                           \
            S[jj_][1] = *reinterpret_cast<const ulonglong2*>(                        \
                &(BASE)[((J0) + jj_) * (STRIDE) + (OBX) + 4]);                       \
        }                                                                            \
    }

// consume a 4-j slab against x float4 at physical col PJ
#define COMP4(S, PJ)                                                                 \
    {                                                                                \
        const int pj_ = (PJ);                                                        \
        _Pragma("unroll")                                                            \
        for (int r = 0; r < ROWS; r++) {                                             \
            const float4 xv = *reinterpret_cast<const float4*>(&sd[r * D + pj_]);    \
            u64 xs;                                                                  \
            xs = pack2(xv.x);                                                        \
            fma2(acc[r][0], xs, S[0][0].x); fma2(acc[r][1], xs, S[0][0].y);          \
            fma2(acc[r][2], xs, S[0][1].x); fma2(acc[r][3], xs, S[0][1].y);          \
            xs = pack2(xv.y);                                                        \
            fma2(acc[r][0], xs, S[1][0].x); fma2(acc[r][1], xs, S[1][0].y);          \
            fma2(acc[r][2], xs, S[1][1].x); fma2(acc[r][3], xs, S[1][1].y);          \
            xs = pack2(xv.z);                                                        \
            fma2(acc[r][0], xs, S[2][0].x); fma2(acc[r][1], xs, S[2][0].y);          \
            fma2(acc[r][2], xs, S[2][1].x); fma2(acc[r][3], xs, S[2][1].y);          \
            xs = pack2(xv.w);                                                        \
            fma2(acc[r][0], xs, S[3][0].x); fma2(acc[r][1], xs, S[3][0].y);          \
            fma2(acc[r][2], xs, S[3][1].x); fma2(acc[r][3], xs, S[3][1].y);          \
        }                                                                            \
    }

// ---------------- main fused kernel ----------------
__global__ __launch_bounds__(THREADS, 1)
void bh_fused_kernel(const float* __restrict__ x,
                     const float* __restrict__ finalB,
                     float* __restrict__ out)
{
    extern __shared__ float sd[];   // ROWS * D floats, swizzled layout
    const int tid = threadIdx.x;
    const size_t row0 = (size_t)blockIdx.x * ROWS;

    // ---- load ROWS rows (coalesced gmem read, swizzled smem store) ----
    {
        const float4* gx = reinterpret_cast<const float4*>(x + row0 * D);
        float4* s4 = reinterpret_cast<float4*>(sd);
        #pragma unroll
        for (int k = 0; k < (ROWS * D / 4) / THREADS; k++) {
            const int f   = tid + k * THREADS;
            const int r   = f >> 10;
            const int cq  = f & 1023;
            const int n   = cq >> 4;
            const int c   = (cq & 15) * 4;
            s4[r * 1024 + (swz(n, c) >> 2)] = gx[f];
        }
    }
    __syncthreads();

    const int g  = tid >> 3;         // group 0..63 (8 threads per group)
    const int ob = (tid & 7) * 8;    // output-col base within group
    const int pb = swz(g, ob);       // physical col base for writes (8-aligned)

    #pragma unroll 1
    for (int stage = 0; stage < 2; stage++) {
        // ---- block-diag 64x64 matmul with C, 4-j slabs, ping-pong LDG ----
        const float* C = g_C + ((size_t)stage * 64 + g) * 64 * 64;

        u64 acc[ROWS][4];
        #pragma unroll
        for (int r = 0; r < ROWS; r++)
            #pragma unroll
            for (int p = 0; p < 4; p++)
                acc[r][p] = 0ull;

        ulonglong2 A[4][2], Bv[4][2];
        LOADC4(A, C, 64, 0, ob)                          // j = 0..3
        #pragma unroll 1
        for (int sb = 0; sb < 8; sb++) {
            const int j0 = sb * 8;
            LOADC4(Bv, C, 64, j0 + 4, ob)                // j+4..j+7
            COMP4(A, swz(g, j0))                         // consume j..j+3
            if (sb < 7) { LOADC4(A, C, 64, j0 + 8, ob) } // j+8..j+11
            COMP4(Bv, swz(g, j0 + 4))                    // consume j+4..j+7
        }
        // block g's region is read/written only by its own group (one warp)
        __syncwarp();
        #pragma unroll
        for (int r = 0; r < ROWS; r++) {
            ulonglong2* sp = reinterpret_cast<ulonglong2*>(&sd[r * D + pb]);
            sp[0] = make_ulonglong2(acc[r][0], acc[r][1]);
            sp[1] = make_ulonglong2(acc[r][2], acc[r][3]);
        }
        __syncthreads();

        // ---- outer H64 (stride-64 across blocks), register-resident ----
        {
            const int hr = tid >> 6;      // row 0..7
            const int hj = tid & 63;      // within-block column
            float v[64];
            #pragma unroll
            for (int m = 0; m < 64; m++)
                v[m] = sd[hr * D + m * 64 + (hj ^ ((m & 7) << 3))];
            #pragma unroll
            for (int h = 1; h < 64; h <<= 1)
                #pragma unroll
                for (int m0 = 0; m0 < 64; m0 += 2*h)
                    #pragma unroll
                    for (int k = 0; k < h; k++) {
                        float a = v[m0+k], b = v[m0+k+h];
                        v[m0+k] = a + b; v[m0+k+h] = a - b;
                    }
            #pragma unroll
            for (int m = 0; m < 64; m++)
                sd[hr * D + m * 64 + (hj ^ ((m & 7) << 3))] = v[m];
        }
        __syncthreads();
    }

    // ---------------- final block-diag 128 x (32x32) matmul -> GMEM ----------------
    {
        const int rect = tid >> 2;        // 0..127 (4 threads per rect)
        const int ob2  = (tid & 3) * 8;
        const int n    = rect >> 1;
        const int cb   = (rect & 1) * 32;
        const float* B = finalB + (size_t)rect * 32 * 32;

        u64 acc[ROWS][4];
        #pragma unroll
        for (int r = 0; r < ROWS; r++)
            #pragma unroll
            for (int p = 0; p < 4; p++)
                acc[r][p] = 0ull;

        ulonglong2 A[4][2], Bv[4][2];
        LOADC4(A, B, 32, 0, ob2)                         // j = 0..3
        #pragma unroll 1
        for (int sb = 0; sb < 4; sb++) {
            const int j0 = sb * 8;
            LOADC4(Bv, B, 32, j0 + 4, ob2)
            COMP4(A, swz(n, cb + j0))
            if (sb < 3) { LOADC4(A, B, 32, j0 + 8, ob2) }
            COMP4(Bv, swz(n, cb + j0 + 4))
        }
        #pragma unroll
        for (int r = 0; r < ROWS; r++) {
            ulonglong2* op = reinterpret_cast<ulonglong2*>(out + (row0 + r) * D + rect * 32 + ob2);
            op[0] = make_ulonglong2(acc[r][0], acc[r][1]);
            op[1] = make_ulonglong2(acc[r][2], acc[r][3]);
        }
    }
}

extern "C" void kernel_launch(void* const* d_in, const int* in_sizes, int n_in,
                              void* d_out, int out_size) {
    const float* x  = (const float*)d_in[0];   // [4,4096,4096] f32
    const float* iB = (const float*)d_in[1];   // [2,64,64,64]  f32
    const float* fB = (const float*)d_in[2];   // [128,32,32]   f32
    float* out = (float*)d_out;                // [4,4096,4096] f32

    prep_kernel<<<64, 128>>>(iB);

    const int smem = ROWS * D * sizeof(float); // 131072 bytes
    cudaFuncSetAttribute(bh_fused_kernel,
                         cudaFuncAttributeMaxDynamicSharedMemorySize, smem);
    const int nrows = 4 * 4096;
    bh_fused_kernel<<<nrows / ROWS, THREADS, smem>>>(x, fB, out);
}